// round 1
// baseline (speedup 1.0000x reference)
#include <cuda_runtime.h>
#include <math.h>

// Problem constants
#define BT    80
#define MAXN  13
#define M_DIM (BT * MAXN)   // 1040
#define K_DIM 26400
#define N_DIM 1024
#define A_DIM 6
#define G_DIM 5

// GEMM tiling
#define BM 64
#define BN 64
#define BK 16
#define TM 4
#define TN 4
#define NTHREADS 256

// Scratch for h = relu(X @ W_emb + b_emb): [1040, 1024] fp32
__device__ float g_H[M_DIM * N_DIM];

// ---------------------------------------------------------------------------
// Kernel 1: h = relu(X[1040,26400] @ W[26400,1024] + b[1024])
// ---------------------------------------------------------------------------
__global__ __launch_bounds__(NTHREADS)
void gemm1_kernel(const float* __restrict__ X,
                  const float* __restrict__ W,
                  const float* __restrict__ bias) {
    __shared__ float As[BK][BM];      // A stored transposed: As[k][m]
    __shared__ float Bs[BK][BN];

    const int bm = blockIdx.y * BM;
    const int bn = blockIdx.x * BN;
    const int tid = threadIdx.x;

    // A-tile load mapping: BM x BK = 64x16 floats = 256 float4, 1 per thread
    const int a_row  = tid >> 2;          // 0..63
    const int a_col4 = (tid & 3) * 4;     // 0,4,8,12
    // B-tile load mapping: BK x BN = 16x64 floats = 256 float4, 1 per thread
    const int b_row  = tid >> 4;          // 0..15
    const int b_col4 = (tid & 15) * 4;    // 0..60

    // Compute mapping: 16x16 threads, each 4x4
    const int ty = tid >> 4;
    const int tx = tid & 15;

    float acc[TM][TN];
    #pragma unroll
    for (int i = 0; i < TM; i++)
        #pragma unroll
        for (int j = 0; j < TN; j++) acc[i][j] = 0.0f;

    const int gm_load = bm + a_row;
    const bool a_valid = (gm_load < M_DIM);
    const float* xrow = X + (long)gm_load * K_DIM;

    for (int k0 = 0; k0 < K_DIM; k0 += BK) {
        // Load A tile (float4), transpose into smem
        float4 av;
        if (a_valid) av = *(const float4*)(xrow + k0 + a_col4);
        else         av = make_float4(0.f, 0.f, 0.f, 0.f);
        As[a_col4 + 0][a_row] = av.x;
        As[a_col4 + 1][a_row] = av.y;
        As[a_col4 + 2][a_row] = av.z;
        As[a_col4 + 3][a_row] = av.w;

        // Load B tile (float4), direct
        float4 bv = *(const float4*)(W + (long)(k0 + b_row) * N_DIM + bn + b_col4);
        *(float4*)&Bs[b_row][b_col4] = bv;

        __syncthreads();

        #pragma unroll
        for (int kk = 0; kk < BK; kk++) {
            float ar[TM], br[TN];
            #pragma unroll
            for (int i = 0; i < TM; i++) ar[i] = As[kk][ty * TM + i];
            #pragma unroll
            for (int j = 0; j < TN; j++) br[j] = Bs[kk][tx * TN + j];
            #pragma unroll
            for (int i = 0; i < TM; i++)
                #pragma unroll
                for (int j = 0; j < TN; j++)
                    acc[i][j] = fmaf(ar[i], br[j], acc[i][j]);
        }
        __syncthreads();
    }

    // Epilogue: bias + ReLU -> g_H
    #pragma unroll
    for (int i = 0; i < TM; i++) {
        int gm = bm + ty * TM + i;
        if (gm >= M_DIM) continue;
        #pragma unroll
        for (int j = 0; j < TN; j++) {
            int gn = bn + tx * TN + j;
            float v = acc[i][j] + bias[gn];
            g_H[(long)gm * N_DIM + gn] = fmaxf(v, 0.0f);
        }
    }
}

// ---------------------------------------------------------------------------
// Kernel 2: per-frame head
//   actions[bt,n,a] = (h[bt,n,:] . w_act[:,a] + b_act[a]) * (n < nvalid)
//   pooled[bt,f]    = max over valid n of h[bt,n,f]
//   activities[bt,g]= pooled[bt,:] . w_acty[:,g] + b_acty[g]
// Output layout: out[0 .. 6239] = actions [80,13,6]; out[6240 ..] = activities [80,5]
// ---------------------------------------------------------------------------
__global__ __launch_bounds__(256)
void head_kernel(const float* __restrict__ w_act,
                 const float* __restrict__ b_act,
                 const float* __restrict__ w_acty,
                 const float* __restrict__ b_acty,
                 const int*   __restrict__ bboxes_num,
                 float* __restrict__ out) {
    const int bt   = blockIdx.x;          // 0..79
    const int tid  = threadIdx.x;         // 256 threads
    const int lane = tid & 31;
    const int warp = tid >> 5;            // 8 warps

    const int nvalid = bboxes_num[bt];
    const float* hbt = g_H + (long)bt * MAXN * N_DIM;

    __shared__ float pooled[N_DIM];

    // Masked max-pool over valid boxes (nvalid >= 1 guaranteed)
    for (int f = tid; f < N_DIM; f += 256) {
        float m = hbt[f];  // n = 0 always valid
        for (int n = 1; n < nvalid; n++)
            m = fmaxf(m, hbt[n * N_DIM + f]);
        pooled[f] = m;
    }

    // Actions: 13*6 = 78 dot products of length 1024, one warp each
    for (int p = warp; p < MAXN * A_DIM; p += 8) {
        int n = p / A_DIM;
        int a = p % A_DIM;
        const float* hr = hbt + n * N_DIM;
        float s = 0.0f;
        for (int f = lane; f < N_DIM; f += 32)
            s = fmaf(hr[f], w_act[f * A_DIM + a], s);
        #pragma unroll
        for (int o = 16; o; o >>= 1) s += __shfl_xor_sync(0xFFFFFFFFu, s, o);
        if (lane == 0) {
            float v = (n < nvalid) ? (s + b_act[a]) : 0.0f;
            out[(bt * MAXN + n) * A_DIM + a] = v;
        }
    }

    __syncthreads();

    // Activities: 5 dot products on pooled
    for (int g = warp; g < G_DIM; g += 8) {
        float s = 0.0f;
        for (int f = lane; f < N_DIM; f += 32)
            s = fmaf(pooled[f], w_acty[f * G_DIM + g], s);
        #pragma unroll
        for (int o = 16; o; o >>= 1) s += __shfl_xor_sync(0xFFFFFFFFu, s, o);
        if (lane == 0)
            out[BT * MAXN * A_DIM + bt * G_DIM + g] = s + b_acty[g];
    }
}

// ---------------------------------------------------------------------------
extern "C" void kernel_launch(void* const* d_in, const int* in_sizes, int n_in,
                              void* d_out, int out_size) {
    const float* X       = (const float*)d_in[0];  // [80,13,26400]
    const float* w_emb   = (const float*)d_in[1];  // [26400,1024]
    const float* b_emb   = (const float*)d_in[2];  // [1024]
    const float* w_act   = (const float*)d_in[3];  // [1024,6]
    const float* b_act   = (const float*)d_in[4];  // [6]
    const float* w_acty  = (const float*)d_in[5];  // [1024,5]
    const float* b_acty  = (const float*)d_in[6];  // [5]
    const int*   bboxes  = (const int*)d_in[7];    // [80]
    float* out = (float*)d_out;

    dim3 grid1(N_DIM / BN, (M_DIM + BM - 1) / BM);   // 16 x 17
    gemm1_kernel<<<grid1, NTHREADS>>>(X, w_emb, b_emb);

    head_kernel<<<BT, 256>>>(w_act, b_act, w_acty, b_acty, bboxes, out);
}

// round 3
// speedup vs baseline: 3.6555x; 3.6555x over previous
#include <cuda_runtime.h>
#include <cuda_bf16.h>
#include <cstdint>
#include <math.h>

// ---------------- problem constants ----------------
#define BT    80
#define MAXN  13
#define M_DIM 1040
#define K_DIM 26400
#define N_DIM 1024
#define A_DIM 6
#define G_DIM 5

// ---------------- GEMM config ----------------
#define K_PAD  26432              // 413 * 64
#define M_PAD  1152               // 9 * 128
#define KC     64                 // K elements per stage chunk (128B rows, SW128)
#define NCHUNK (K_PAD / KC)       // 413
#define GM 128
#define GN 64
#define STAGES 3

#define A_TILE_BYTES (128 * 128)         // 128 rows x 128B = 16KB
#define B_TILE_BYTES (64 * 128)          // 64 rows x 128B  = 8KB
#define STAGE_BYTES  (2 * A_TILE_BYTES + 2 * B_TILE_BYTES)   // Ah,Al,Bh,Bl = 48KB
#define OFF_AH 0
#define OFF_AL A_TILE_BYTES
#define OFF_BH (2 * A_TILE_BYTES)
#define OFF_BL (2 * A_TILE_BYTES + B_TILE_BYTES)
#define SMEM_TOTAL (STAGES * STAGE_BYTES)   // 147456

// ---------------- device scratch (static: allocation-guard safe) ----------------
__device__ __align__(128) __nv_bfloat16 g_Xh[(size_t)M_PAD * K_PAD];
__device__ __align__(128) __nv_bfloat16 g_Xl[(size_t)M_PAD * K_PAD];
__device__ __align__(128) __nv_bfloat16 g_Wh[(size_t)N_DIM * K_PAD];
__device__ __align__(128) __nv_bfloat16 g_Wl[(size_t)N_DIM * K_PAD];
__device__ float g_H[(size_t)M_DIM * N_DIM];

// ---------------- helpers ----------------
__device__ __forceinline__ uint32_t smem_u32(const void* p) {
    uint32_t a;
    asm("{ .reg .u64 t; cvta.to.shared.u64 t, %1; cvt.u32.u64 %0, t; }" : "=r"(a) : "l"(p));
    return a;
}
__device__ __forceinline__ void cp_async16(uint32_t dst, const void* src) {
    asm volatile("cp.async.cg.shared.global [%0], [%1], 16;" :: "r"(dst), "l"(src));
}
#define CP_COMMIT() asm volatile("cp.async.commit_group;" ::: "memory")
#define CP_WAIT1()  asm volatile("cp.async.wait_group 1;" ::: "memory")

#define LDSM_X4(r0, r1, r2, r3, addr) \
    asm volatile("ldmatrix.sync.aligned.m8n8.x4.shared.b16 {%0,%1,%2,%3}, [%4];" \
        : "=r"(r0), "=r"(r1), "=r"(r2), "=r"(r3) : "r"(addr))

__device__ __forceinline__ void mma_bf16(float* c, const uint32_t* a, const uint32_t* b) {
    asm volatile(
        "mma.sync.aligned.m16n8k16.row.col.f32.bf16.bf16.f32 "
        "{%0,%1,%2,%3}, {%4,%5,%6,%7}, {%8,%9}, {%0,%1,%2,%3};"
        : "+f"(c[0]), "+f"(c[1]), "+f"(c[2]), "+f"(c[3])
        : "r"(a[0]), "r"(a[1]), "r"(a[2]), "r"(a[3]), "r"(b[0]), "r"(b[1]));
}

// swizzled address inside one 128B-row tile: chunk index c (16B units), row
__device__ __forceinline__ uint32_t swz_addr(uint32_t tile_base, int row, int c) {
    return tile_base + (uint32_t)(row * 128) + (uint32_t)((c ^ (row & 7)) << 4);
}

// Fill a tile of `rows` rows x 128B from global bf16 [*, K_PAD], 256 threads
template <int ROWS, int ITERS>
__device__ __forceinline__ void fill_tile(uint32_t smem_tile, const __nv_bfloat16* gbase,
                                          int row0, int k0, int tid) {
    const char* base = (const char*)gbase;
    #pragma unroll
    for (int i = 0; i < ITERS; i++) {
        int idx = tid + i * 256;          // chunk id
        int row = idx >> 3;
        int c   = idx & 7;                // 16B chunk within row
        const char* src = base + ((size_t)(row0 + row) * K_PAD + (size_t)k0) * 2 + c * 16;
        cp_async16(swz_addr(smem_tile, row, c), src);
    }
}

// ---------------- Kernel: fp32 -> bf16 hi/lo split of X ----------------
__global__ __launch_bounds__(256)
void convert_x_kernel(const float* __restrict__ X) {
    size_t t = (size_t)blockIdx.x * blockDim.x + threadIdx.x;
    const size_t total = (size_t)M_DIM * (K_DIM / 4);
    if (t >= total) return;
    int m  = (int)(t / (K_DIM / 4));
    int kk = (int)(t % (K_DIM / 4)) * 4;
    float4 v = *(const float4*)(X + (size_t)m * K_DIM + kk);
    float f[4] = {v.x, v.y, v.z, v.w};
    uint32_t hi[2], lo[2];
    #pragma unroll
    for (int p = 0; p < 2; p++) {
        __nv_bfloat16 h0 = __float2bfloat16(f[2*p+0]);
        __nv_bfloat16 h1 = __float2bfloat16(f[2*p+1]);
        __nv_bfloat16 l0 = __float2bfloat16(f[2*p+0] - __bfloat162float(h0));
        __nv_bfloat16 l1 = __float2bfloat16(f[2*p+1] - __bfloat162float(h1));
        hi[p] = (uint32_t)__bfloat16_as_ushort(h0) | ((uint32_t)__bfloat16_as_ushort(h1) << 16);
        lo[p] = (uint32_t)__bfloat16_as_ushort(l0) | ((uint32_t)__bfloat16_as_ushort(l1) << 16);
    }
    size_t o = (size_t)m * K_PAD + kk;
    *(uint2*)(g_Xh + o) = make_uint2(hi[0], hi[1]);
    *(uint2*)(g_Xl + o) = make_uint2(lo[0], lo[1]);
}

// ---------------- Kernel: transpose + split W [K,N] -> Wh/Wl [N, K_PAD] ----------------
__global__ __launch_bounds__(256)
void convert_w_kernel(const float* __restrict__ W) {
    __shared__ float s[64][33];
    const int k0 = blockIdx.x * 64;
    const int n0 = blockIdx.y * 32;
    const int tid = threadIdx.x;

    {
        int kr = tid >> 2;
        int nb = (tid & 3) * 8;
        int k = k0 + kr;
        if (k < K_DIM) {
            float4 a = *(const float4*)(W + (size_t)k * N_DIM + n0 + nb);
            float4 b = *(const float4*)(W + (size_t)k * N_DIM + n0 + nb + 4);
            s[kr][nb+0]=a.x; s[kr][nb+1]=a.y; s[kr][nb+2]=a.z; s[kr][nb+3]=a.w;
            s[kr][nb+4]=b.x; s[kr][nb+5]=b.y; s[kr][nb+6]=b.z; s[kr][nb+7]=b.w;
        } else {
            #pragma unroll
            for (int i = 0; i < 8; i++) s[kr][nb+i] = 0.0f;
        }
    }
    __syncthreads();

    {
        int nr = tid >> 3;
        int kb = (tid & 7) * 8;
        uint32_t hi[4], lo[4];
        #pragma unroll
        for (int p = 0; p < 4; p++) {
            float f0 = s[kb + 2*p + 0][nr];
            float f1 = s[kb + 2*p + 1][nr];
            __nv_bfloat16 h0 = __float2bfloat16(f0);
            __nv_bfloat16 h1 = __float2bfloat16(f1);
            __nv_bfloat16 l0 = __float2bfloat16(f0 - __bfloat162float(h0));
            __nv_bfloat16 l1 = __float2bfloat16(f1 - __bfloat162float(h1));
            hi[p] = (uint32_t)__bfloat16_as_ushort(h0) | ((uint32_t)__bfloat16_as_ushort(h1) << 16);
            lo[p] = (uint32_t)__bfloat16_as_ushort(l0) | ((uint32_t)__bfloat16_as_ushort(l1) << 16);
        }
        size_t o = (size_t)(n0 + nr) * K_PAD + k0 + kb;
        *(uint4*)(g_Wh + o) = make_uint4(hi[0], hi[1], hi[2], hi[3]);
        *(uint4*)(g_Wl + o) = make_uint4(lo[0], lo[1], lo[2], lo[3]);
    }
}

// ---------------- Kernel: mma.sync bf16 GEMM, 3-term split ----------------
// g_H = relu(Xh*Wh^T + Xh*Wl^T + Xl*Wh^T + bias)
__global__ void __launch_bounds__(256, 1)
gemm_kernel(const float* __restrict__ bias) {
    extern __shared__ char smem[];
    const uint32_t sb = smem_u32(smem);
    const int tid  = threadIdx.x;
    const int lane = tid & 31;
    const int wid  = tid >> 5;
    const int bm = blockIdx.y * GM;
    const int bn = blockIdx.x * GN;
    const int m_off = (wid & 3) * 32;   // 4 warps down M
    const int n_off = (wid >> 2) * 32;  // 2 warps across N

    float acc[2][4][4];
    #pragma unroll
    for (int mi = 0; mi < 2; mi++)
        #pragma unroll
        for (int ni = 0; ni < 4; ni++)
            #pragma unroll
            for (int q = 0; q < 4; q++) acc[mi][ni][q] = 0.0f;

    // ldmatrix lane addressing (within tile)
    const int aRow0 = m_off + (lane & 15);
    const int cA    = lane >> 4;            // 0/1 -> k chunk select
    const int bRowBase = n_off + ((lane & 16) >> 1) + (lane & 7);
    const int cB    = (lane >> 3) & 1;

    // prologue: stages 0,1
    #pragma unroll
    for (int j = 0; j < STAGES - 1; j++) {
        uint32_t st = sb + j * STAGE_BYTES;
        fill_tile<128, 4>(st + OFF_AH, g_Xh, bm, j * KC, tid);
        fill_tile<128, 4>(st + OFF_AL, g_Xl, bm, j * KC, tid);
        fill_tile<64, 2>(st + OFF_BH, g_Wh, bn, j * KC, tid);
        fill_tile<64, 2>(st + OFF_BL, g_Wl, bn, j * KC, tid);
        CP_COMMIT();
    }

    for (int j = 0; j < NCHUNK; j++) {
        CP_WAIT1();            // stage j complete
        __syncthreads();       // visible to all warps; prior compute done

        // prefetch stage j+2 (overwrites buffer of stage j-1)
        if (j + 2 < NCHUNK) {
            uint32_t st = sb + ((j + 2) % STAGES) * STAGE_BYTES;
            fill_tile<128, 4>(st + OFF_AH, g_Xh, bm, (j + 2) * KC, tid);
            fill_tile<128, 4>(st + OFF_AL, g_Xl, bm, (j + 2) * KC, tid);
            fill_tile<64, 2>(st + OFF_BH, g_Wh, bn, (j + 2) * KC, tid);
            fill_tile<64, 2>(st + OFF_BL, g_Wl, bn, (j + 2) * KC, tid);
        }
        CP_COMMIT();           // unconditional: keeps per-thread group counts uniform

        const uint32_t st = sb + (j % STAGES) * STAGE_BYTES;
        #pragma unroll
        for (int kk = 0; kk < 4; kk++) {
            uint32_t ah[2][4], al[2][4], bh[2][4], bl[2][4];
            #pragma unroll
            for (int mi = 0; mi < 2; mi++) {
                uint32_t adr_h = swz_addr(st + OFF_AH, aRow0 + mi * 16, kk * 2 + cA);
                uint32_t adr_l = swz_addr(st + OFF_AL, aRow0 + mi * 16, kk * 2 + cA);
                LDSM_X4(ah[mi][0], ah[mi][1], ah[mi][2], ah[mi][3], adr_h);
                LDSM_X4(al[mi][0], al[mi][1], al[mi][2], al[mi][3], adr_l);
            }
            #pragma unroll
            for (int ni2 = 0; ni2 < 2; ni2++) {
                uint32_t adr_h = swz_addr(st + OFF_BH, bRowBase + ni2 * 16, kk * 2 + cB);
                uint32_t adr_l = swz_addr(st + OFF_BL, bRowBase + ni2 * 16, kk * 2 + cB);
                LDSM_X4(bh[ni2][0], bh[ni2][1], bh[ni2][2], bh[ni2][3], adr_h);
                LDSM_X4(bl[ni2][0], bl[ni2][1], bl[ni2][2], bl[ni2][3], adr_l);
            }
            #pragma unroll
            for (int mi = 0; mi < 2; mi++) {
                #pragma unroll
                for (int ni = 0; ni < 4; ni++) {
                    const uint32_t* bfh = &bh[ni >> 1][(ni & 1) * 2];
                    const uint32_t* bfl = &bl[ni >> 1][(ni & 1) * 2];
                    mma_bf16(acc[mi][ni], ah[mi], bfh);   // Ah*Bh
                    mma_bf16(acc[mi][ni], ah[mi], bfl);   // Ah*Bl
                    mma_bf16(acc[mi][ni], al[mi], bfh);   // Al*Bh
                }
            }
        }
        __syncthreads();       // all warps done reading stage j before it is refilled
    }

    // epilogue: bias + ReLU -> g_H
    #pragma unroll
    for (int mi = 0; mi < 2; mi++) {
        #pragma unroll
        for (int ni = 0; ni < 4; ni++) {
            int gm0 = bm + m_off + mi * 16 + (lane >> 2);
            int gn  = bn + n_off + ni * 8 + (lane & 3) * 2;
            float b0 = bias[gn], b1 = bias[gn + 1];
            if (gm0 < M_DIM) {
                float2 v;
                v.x = fmaxf(acc[mi][ni][0] + b0, 0.0f);
                v.y = fmaxf(acc[mi][ni][1] + b1, 0.0f);
                *(float2*)(g_H + (size_t)gm0 * N_DIM + gn) = v;
            }
            int gm1 = gm0 + 8;
            if (gm1 < M_DIM) {
                float2 v;
                v.x = fmaxf(acc[mi][ni][2] + b0, 0.0f);
                v.y = fmaxf(acc[mi][ni][3] + b1, 0.0f);
                *(float2*)(g_H + (size_t)gm1 * N_DIM + gn) = v;
            }
        }
    }
}

// ---------------- Kernel: per-frame head ----------------
__global__ __launch_bounds__(256)
void head_kernel(const float* __restrict__ w_act,
                 const float* __restrict__ b_act,
                 const float* __restrict__ w_acty,
                 const float* __restrict__ b_acty,
                 const int*   __restrict__ bboxes_num,
                 float* __restrict__ out) {
    const int bt   = blockIdx.x;
    const int tid  = threadIdx.x;
    const int lane = tid & 31;
    const int warp = tid >> 5;

    const int nvalid = bboxes_num[bt];
    const float* hbt = g_H + (size_t)bt * MAXN * N_DIM;

    __shared__ float pooled[N_DIM];

    for (int f = tid; f < N_DIM; f += 256) {
        float m = hbt[f];
        for (int n = 1; n < nvalid; n++) m = fmaxf(m, hbt[n * N_DIM + f]);
        pooled[f] = m;
    }

    for (int p = warp; p < MAXN * A_DIM; p += 8) {
        int n = p / A_DIM;
        int a = p % A_DIM;
        const float* hr = hbt + n * N_DIM;
        float s = 0.0f;
        for (int f = lane; f < N_DIM; f += 32)
            s = fmaf(hr[f], w_act[f * A_DIM + a], s);
        #pragma unroll
        for (int o = 16; o; o >>= 1) s += __shfl_xor_sync(0xFFFFFFFFu, s, o);
        if (lane == 0)
            out[(bt * MAXN + n) * A_DIM + a] = (n < nvalid) ? (s + b_act[a]) : 0.0f;
    }

    __syncthreads();

    for (int g = warp; g < G_DIM; g += 8) {
        float s = 0.0f;
        for (int f = lane; f < N_DIM; f += 32)
            s = fmaf(pooled[f], w_acty[f * G_DIM + g], s);
        #pragma unroll
        for (int o = 16; o; o >>= 1) s += __shfl_xor_sync(0xFFFFFFFFu, s, o);
        if (lane == 0)
            out[BT * MAXN * A_DIM + bt * G_DIM + g] = s + b_acty[g];
    }
}

// ---------------- launch ----------------
extern "C" void kernel_launch(void* const* d_in, const int* in_sizes, int n_in,
                              void* d_out, int out_size) {
    const float* X      = (const float*)d_in[0];
    const float* w_emb  = (const float*)d_in[1];
    const float* b_emb  = (const float*)d_in[2];
    const float* w_act  = (const float*)d_in[3];
    const float* b_act  = (const float*)d_in[4];
    const float* w_acty = (const float*)d_in[5];
    const float* b_acty = (const float*)d_in[6];
    const int*   bboxes = (const int*)d_in[7];
    float* out = (float*)d_out;

    cudaFuncSetAttribute(gemm_kernel, cudaFuncAttributeMaxDynamicSharedMemorySize, SMEM_TOTAL);

    {
        size_t total = (size_t)M_DIM * (K_DIM / 4);
        int blocks = (int)((total + 255) / 256);
        convert_x_kernel<<<blocks, 256>>>(X);
    }
    {
        dim3 g(K_PAD / 64, N_DIM / 32);
        convert_w_kernel<<<g, 256>>>(w_emb);
    }
    {
        dim3 g(N_DIM / GN, M_PAD / GM);   // 16 x 9 = 144 CTAs
        gemm_kernel<<<g, 256, SMEM_TOTAL>>>(b_emb);
    }
    head_kernel<<<BT, 256>>>(w_act, b_act, w_acty, b_acty, bboxes, out);
}